// round 6
// baseline (speedup 1.0000x reference)
#include <cuda_runtime.h>
#include <cstdint>

// FP16 pulse (16 floats of 0.0/1.0) -> FP8 E4M3 pulse (8 floats).
// HBM-bound streaming: 1.074 GB in + 0.537 GB out, no reuse. Floor ~201us @ 8TB/s.
// R2 (persistent + .cs hints) regressed to 255us kernel: loop-carried serialization
// + evict-first stores killed DRAM MLP. R3/R4: back to one-shot grid, default cache
// ops, but 2 elements/thread with all 8 LDG.128 front-batched (MLP 4 -> 8,
// 4KB contiguous per warp load batch, half the CTAs). R4 = R3 resubmit (infra fail).

__device__ __forceinline__ unsigned BITU(unsigned u) {
    // inputs are exactly 0.0f (0x00000000) or 1.0f (0x3F800000); bit 29 selects
    return (u >> 29) & 1u;
}

// Convert one element given its 4 input words; returns packed 8-bit result S|E4|M3.
__device__ __forceinline__ unsigned convert(uint4 w0, uint4 w1, uint4 w2, uint4 w3) {
    unsigned s = BITU(w0.x);
    unsigned e = (BITU(w0.y) << 4) | (BITU(w0.z) << 3) | (BITU(w0.w) << 2) |
                 (BITU(w1.x) << 1) |  BITU(w1.y);
    unsigned m = (BITU(w1.z) << 9) | (BITU(w1.w) << 8) |
                 (BITU(w2.x) << 7) | (BITU(w2.y) << 6) |
                 (BITU(w2.z) << 5) | (BITU(w2.w) << 4) |
                 (BITU(w3.x) << 3) | (BITU(w3.y) << 2) |
                 (BITU(w3.z) << 1) |  BITU(w3.w);

    // normal path (fp16 exp 9..22): RNE(m >> 7), carry bumps exponent
    unsigned keep = m >> 7;
    unsigned sticky_n = (m & 63u) ? 1u : 0u;
    unsigned up_n = ((m >> 6) & 1u) & (sticky_n | (keep & 1u));
    unsigned mr = keep + up_n;                               // 0..8
    unsigned norm = (((e - 8u) + (mr >> 3)) << 3) | (mr & 7u);

    // subnormal path (fp16 exp 5..8): msub = RNE((1024+m) >> (16-e));
    // msub==8 promotes to E=1,M=0 == packed 8, so msub IS the packed E<<3|M.
    unsigned x = 1024u + m;
    int kk_i = 16 - (int)e;
    unsigned kk = (unsigned)min(max(kk_i, 8), 11);
    unsigned keep2 = x >> kk;
    unsigned low = (1u << (kk - 1u)) - 1u;
    unsigned sticky_s = (x & low) ? 1u : 0u;
    unsigned up_s = ((x >> (kk - 1u)) & 1u) & (sticky_s | (keep2 & 1u));
    unsigned msub = keep2 + up_s;

    unsigned em = (e > 22u) ? 0x7Eu
                : (e < 5u)  ? 0u
                : (e <= 8u) ? msub
                :             norm;
    return (s << 7) | em;
}

__device__ __forceinline__ void expand(unsigned R, uint4& o0, uint4& o1) {
    const unsigned ONE = 0x3F800000u;
    o0.x = ((R >> 7) & 1u) * ONE;
    o0.y = ((R >> 6) & 1u) * ONE;
    o0.z = ((R >> 5) & 1u) * ONE;
    o0.w = ((R >> 4) & 1u) * ONE;
    o1.x = ((R >> 3) & 1u) * ONE;
    o1.y = ((R >> 2) & 1u) * ONE;
    o1.z = ((R >> 1) & 1u) * ONE;
    o1.w = ( R       & 1u) * ONE;
}

__global__ void __launch_bounds__(256)
fp16_to_fp8_kernel(const uint4* __restrict__ in, uint4* __restrict__ out, int n2) {
    // each thread handles elements 2*t and 2*t+1 (8 contiguous uint4 loads)
    int t = blockIdx.x * blockDim.x + threadIdx.x;
    if (t >= n2) return;
    long base = 8L * t;

    // front-batch all 8 LDG.128 for maximum outstanding-load depth
    const uint4 a0 = in[base + 0];
    const uint4 a1 = in[base + 1];
    const uint4 a2 = in[base + 2];
    const uint4 a3 = in[base + 3];
    const uint4 b0 = in[base + 4];
    const uint4 b1 = in[base + 5];
    const uint4 b2 = in[base + 6];
    const uint4 b3 = in[base + 7];

    unsigned Ra = convert(a0, a1, a2, a3);
    unsigned Rb = convert(b0, b1, b2, b3);

    uint4 o0, o1, o2, o3;
    expand(Ra, o0, o1);
    expand(Rb, o2, o3);

    long ob = 4L * t;
    out[ob + 0] = o0;
    out[ob + 1] = o1;
    out[ob + 2] = o2;
    out[ob + 3] = o3;
}

extern "C" void kernel_launch(void* const* d_in, const int* in_sizes, int n_in,
                              void* d_out, int out_size) {
    const uint4* in = (const uint4*)d_in[0];
    uint4* out = (uint4*)d_out;
    int n = in_sizes[0] / 16;        // elements
    int n2 = n / 2;                  // 2 elements per thread (n is even: 4096*4096)
    int threads = 256;
    int blocks = (n2 + threads - 1) / threads;   // 32768
    fp16_to_fp8_kernel<<<blocks, threads>>>(in, out, n2);
}

// round 8
// speedup vs baseline: 1.3423x; 1.3423x over previous
#include <cuda_runtime.h>
#include <cstdint>

// FP16 pulse (16 floats 0.0/1.0) -> FP8 E4M3 pulse (8 floats). HBM-bound stream.
// R1: 226.9us (DRAM 89.9%, L1 66.9%). R3: 303us — 128B lane stride blew up L1
// wavefronts (93.2%). R6/R7: fully warp-coalesced LDG.32 loads (1 wf/instr) +
// __ballot_sync bit-transpose + __brev unpack + shuffle-aligned STG.128 stores.
// L1 wavefronts per warp-tile: 80 -> 24. R7 = R6 resubmit (infra fail).

__global__ void __launch_bounds__(256)
fp16_to_fp8_kernel(const float* __restrict__ in, uint4* __restrict__ out, int nwarp) {
    int gt   = blockIdx.x * 256 + threadIdx.x;
    int w    = gt >> 5;          // global warp id: owns elements [32w, 32w+32)
    int lane = gt & 31;
    if (w >= nwarp) return;      // uniform per warp

    // ---- coalesced loads: lane L takes float word 512w + 32k + L
    const float* p = in + (size_t)w * 512 + lane;
    float f[16];
#pragma unroll
    for (int k = 0; k < 16; k++) f[k] = p[32 * k];

    // ---- ballot transpose: B[k] bit L = pulse bit (L&15) of element 32w+2k+(L>=16)
    unsigned B[16];
#pragma unroll
    for (int k = 0; k < 16; k++) B[k] = __ballot_sync(0xffffffffu, f[k] != 0.0f);

    // ---- lane L's element is 32w+L: halfword from B[L>>1], half (L&1)
    unsigned idx = (unsigned)(lane >> 1);
    unsigned u0 = (idx & 1) ? B[1]  : B[0];
    unsigned u1 = (idx & 1) ? B[3]  : B[2];
    unsigned u2 = (idx & 1) ? B[5]  : B[4];
    unsigned u3 = (idx & 1) ? B[7]  : B[6];
    unsigned u4 = (idx & 1) ? B[9]  : B[8];
    unsigned u5 = (idx & 1) ? B[11] : B[10];
    unsigned u6 = (idx & 1) ? B[13] : B[12];
    unsigned u7 = (idx & 1) ? B[15] : B[14];
    unsigned v0 = (idx & 2) ? u1 : u0;
    unsigned v1 = (idx & 2) ? u3 : u2;
    unsigned v2 = (idx & 2) ? u5 : u4;
    unsigned v3 = (idx & 2) ? u7 : u6;
    unsigned x0 = (idx & 4) ? v1 : v0;
    unsigned x1 = (idx & 4) ? v3 : v2;
    unsigned Bw = (idx & 8) ? x1 : x0;
    unsigned h  = (Bw >> ((lane & 1) * 16)) & 0xFFFFu;

    // ---- unpack: h bit b = pulse bit b ([S,E4..E0,M9..M0] MSB-first)
    unsigned rev = __brev(h);
    unsigned s = rev >> 31;
    unsigned e = (rev >> 26) & 31u;
    unsigned m = (rev >> 16) & 0x3FFu;

    // ---- normal path (fp16 exp 9..22): RNE(m >> 7), carry bumps exponent
    unsigned keep = m >> 7;
    unsigned sticky_n = (m & 63u) ? 1u : 0u;
    unsigned up_n = ((m >> 6) & 1u) & (sticky_n | (keep & 1u));
    unsigned mr = keep + up_n;                               // 0..8
    unsigned norm = (((e - 8u) + (mr >> 3)) << 3) | (mr & 7u);

    // ---- subnormal path (fp16 exp 5..8): msub = RNE((1024+m) >> (16-e));
    // msub==8 promotes to E=1,M=0 == packed 8, so msub IS the packed E<<3|M
    unsigned xx = 1024u + m;
    int kk_i = 16 - (int)e;
    unsigned kk = (unsigned)min(max(kk_i, 8), 11);
    unsigned keep2 = xx >> kk;
    unsigned low = (1u << (kk - 1u)) - 1u;
    unsigned sticky_s = (xx & low) ? 1u : 0u;
    unsigned up_s = ((xx >> (kk - 1u)) & 1u) & (sticky_s | (keep2 & 1u));
    unsigned msub = keep2 + up_s;

    unsigned em = (e > 22u) ? 0x7Eu
                : (e < 5u)  ? 0u
                : (e <= 8u) ? msub
                :             norm;
    unsigned R = (s << 7) | em;      // packed S|E4|M3 for element 32w+lane

    // ---- coalesced stores: out uint4 index 64w+q, q<->(elem q>>1, half q&1)
    // lane L stores q=L (needs R of elem L>>1) and q=32+L (elem 16+(L>>1))
    unsigned Ra = __shfl_sync(0xffffffffu, R, lane >> 1);
    unsigned Rb = __shfl_sync(0xffffffffu, R, 16 + (lane >> 1));
    int bsh = 7 - 4 * (lane & 1);    // half 0: bits 7..4 ; half 1: bits 3..0
    const unsigned ONE = 0x3F800000u;
    uint4 oA, oB;
    oA.x = ((Ra >> bsh)       & 1u) * ONE;
    oA.y = ((Ra >> (bsh - 1)) & 1u) * ONE;
    oA.z = ((Ra >> (bsh - 2)) & 1u) * ONE;
    oA.w = ((Ra >> (bsh - 3)) & 1u) * ONE;
    oB.x = ((Rb >> bsh)       & 1u) * ONE;
    oB.y = ((Rb >> (bsh - 1)) & 1u) * ONE;
    oB.z = ((Rb >> (bsh - 2)) & 1u) * ONE;
    oB.w = ((Rb >> (bsh - 3)) & 1u) * ONE;

    uint4* q = out + (size_t)w * 64;
    q[lane]      = oA;
    q[32 + lane] = oB;
}

extern "C" void kernel_launch(void* const* d_in, const int* in_sizes, int n_in,
                              void* d_out, int out_size) {
    const float* in = (const float*)d_in[0];
    uint4* out = (uint4*)d_out;
    int n = in_sizes[0] / 16;            // elements (4096*4096)
    int nwarp = n / 32;                  // 32 elements per warp; n divisible by 32
    int threads = 256;
    int blocks = (nwarp * 32 + threads - 1) / threads;   // 65536
    fp16_to_fp8_kernel<<<blocks, threads>>>(in, out, nwarp);
}